// round 8
// baseline (speedup 1.0000x reference)
#include <cuda_runtime.h>

// VectorP1FunctionSpace: P1 FEM interpolation on a structured 32x32
// triangulation of [0,1]^2 (nvert = 33*33 = 1089).
//
// basis[v] = min_k relu(x.W[v,k]+c[v,k]) is the P1 hat of vertex v: exactly 0
// for vertices outside the containing triangle (relu floor), equal to the
// barycentric coordinate for the 3 triangle vertices. Locate cell
// analytically, 3 barycentric weights, gather 3 entries each of wx/wy.
// Mechanism verified exactly in R4 (min-of-6 replication, rel_err 5e-8).
//
// R7: 4 points/thread, 64 CTAs x 64 threads. R5/R6 produced bit-identical
// kernel durations (5.152us) despite different instruction streams ->
// duration is fixed-overhead dominated (CTA dispatch, per-launch L1D flush,
// DVFS). This round tests the last body-side lever: halving CTA count and
// deepening per-thread MLP (12 concurrent L2 gathers).

static __device__ __forceinline__ void eval_point(float px, float py,
                                                  const float* __restrict__ wx,
                                                  const float* __restrict__ wy,
                                                  float& ox, float& oy) {
    float fx = px * 32.0f;
    float fy = py * 32.0f;
    int i = (int)fx;  i = i < 0 ? 0 : (i > 31 ? 31 : i);
    int j = (int)fy;  j = j < 0 ? 0 : (j > 31 ? 31 : j);
    float u = fx - (float)i;
    float v = fy - (float)j;

    int v00 = i * 33 + j;        // vertex (i,j)
    int v11 = v00 + 34;          // (i+1,j+1) — shared by both triangles

    bool lower = (u >= v);
    int v3 = lower ? (v00 + 33) : (v00 + 1);   // v10 (lower) / v01 (upper)

    float b00 = lower ? (1.0f - u) : (1.0f - v);
    float b11 = lower ? v : u;
    float b3  = lower ? (u - v) : (v - u);

    ox = fmaf(b00, __ldg(wx + v00),
         fmaf(b11, __ldg(wx + v11),
              b3 * __ldg(wx + v3)));
    oy = fmaf(b00, __ldg(wy + v00),
         fmaf(b11, __ldg(wy + v11),
              b3 * __ldg(wy + v3)));
}

__global__ void __launch_bounds__(64)
VectorP1FunctionSpace_5342939316636_kernel(const float4* __restrict__ x2,
                                           const float* __restrict__ wx,
                                           const float* __restrict__ wy,
                                           float4* __restrict__ out2,
                                           int npair) {
    int idx = (blockIdx.x * blockDim.x + threadIdx.x) * 2;  // 2 float4 = 4 pts

    if (idx + 1 < npair) {
        // Front-batch both input loads (MLP), then both gather fans.
        float4 pa = x2[idx];
        float4 pb = x2[idx + 1];

        float oxa0, oya0, oxa1, oya1, oxb0, oyb0, oxb1, oyb1;
        eval_point(pa.x, pa.y, wx, wy, oxa0, oya0);
        eval_point(pa.z, pa.w, wx, wy, oxa1, oya1);
        eval_point(pb.x, pb.y, wx, wy, oxb0, oyb0);
        eval_point(pb.z, pb.w, wx, wy, oxb1, oyb1);

        out2[idx]     = make_float4(oxa0, oya0, oxa1, oya1);
        out2[idx + 1] = make_float4(oxb0, oyb0, oxb1, oyb1);
    } else if (idx < npair) {
        float4 pa = x2[idx];
        float ox0, oy0, ox1, oy1;
        eval_point(pa.x, pa.y, wx, wy, ox0, oy0);
        eval_point(pa.z, pa.w, wx, wy, ox1, oy1);
        out2[idx] = make_float4(ox0, oy0, ox1, oy1);
    }
}

extern "C" void kernel_launch(void* const* d_in, const int* in_sizes, int n_in,
                              void* d_out, int out_size) {
    const float4* x2  = (const float4*)d_in[0];  // [B,N,2] fp32, 2 pts/float4
    // d_in[1] = W [1089,6,2], d_in[2] = C [1089,6] — unused (analytic)
    const float*  wx  = (const float*)d_in[3];   // [1089]
    const float*  wy  = (const float*)d_in[4];   // [1089]
    float4* out2 = (float4*)d_out;               // [B,N,2] fp32

    int npair   = in_sizes[0] / 4;               // 8192 float4 pairs
    int nthread = (npair + 1) / 2;               // 4096 threads, 4 pts each
    int threads = 64;
    int blocks  = (nthread + threads - 1) / threads;  // 64 blocks
    VectorP1FunctionSpace_5342939316636_kernel<<<blocks, threads>>>(
        x2, wx, wy, out2, npair);
}

// round 9
// speedup vs baseline: 1.1436x; 1.1436x over previous
#include <cuda_runtime.h>

// VectorP1FunctionSpace: P1 FEM interpolation on a structured 32x32
// triangulation of [0,1]^2 (nvert = 33*33 = 1089).
//
// basis[v] = min_k relu(x.W[v,k]+c[v,k]) is the P1 hat of vertex v: exactly 0
// outside the containing triangle (relu floor), equal to the barycentric
// coordinate for the 3 triangle vertices. Locate cell analytically, 3
// barycentric weights, gather 3 entries each of wx/wy. Mechanism verified
// exactly in R4 (min-of-6 replication, rel_err 5e-8).
//
// R8: smem-stage the full wx/wy tables (8.7 KB/CTA). The cooperative fill is
// independent of the per-thread x load, so the two ~260-cycle L2 round trips
// overlap; the 6 data-dependent gathers become 29-cycle LDS instead of
// 260-cycle L2 LDG, shortening the latency-critical path (~200 cycles) of
// this launch-latency-dominated kernel.

#define NVERT 1089

__global__ void __launch_bounds__(128)
VectorP1FunctionSpace_5342939316636_kernel(const float2* __restrict__ x,
                                           const float* __restrict__ wx,
                                           const float* __restrict__ wy,
                                           float2* __restrict__ out,
                                           int n) {
    __shared__ float swx[NVERT];
    __shared__ float swy[NVERT];

    int tid = threadIdx.x;

    // Start the (independent) x load first so it overlaps the smem fill.
    int idx = blockIdx.x * blockDim.x + tid;
    float2 p = (idx < n) ? x[idx] : make_float2(0.0f, 0.0f);

    // Cooperative fill: 1089 floats x2, 128 threads -> 9 iters, coalesced.
#pragma unroll
    for (int k = tid; k < NVERT; k += 128) {
        swx[k] = __ldg(wx + k);
        swy[k] = __ldg(wy + k);
    }
    __syncthreads();

    if (idx >= n) return;

    float fx = p.x * 32.0f;
    float fy = p.y * 32.0f;
    int i = (int)fx;  i = i < 0 ? 0 : (i > 31 ? 31 : i);
    int j = (int)fy;  j = j < 0 ? 0 : (j > 31 ? 31 : j);
    float u = fx - (float)i;
    float v = fy - (float)j;

    int v00 = i * 33 + j;        // vertex (i,j)
    int v11 = v00 + 34;          // (i+1,j+1) — shared by both triangles

    bool lower = (u >= v);
    int v3 = lower ? (v00 + 33) : (v00 + 1);   // v10 (lower) / v01 (upper)

    float b00 = lower ? (1.0f - u) : (1.0f - v);
    float b11 = lower ? v : u;
    float b3  = lower ? (u - v) : (v - u);

    float ox = fmaf(b00, swx[v00], fmaf(b11, swx[v11], b3 * swx[v3]));
    float oy = fmaf(b00, swy[v00], fmaf(b11, swy[v11], b3 * swy[v3]));

    out[idx] = make_float2(ox, oy);
}

extern "C" void kernel_launch(void* const* d_in, const int* in_sizes, int n_in,
                              void* d_out, int out_size) {
    const float2* x  = (const float2*)d_in[0];  // [B,N,2] fp32
    // d_in[1] = W [1089,6,2], d_in[2] = C [1089,6] — unused (analytic)
    const float*  wx = (const float*)d_in[3];   // [1089]
    const float*  wy = (const float*)d_in[4];   // [1089]
    float2* out = (float2*)d_out;               // [B,N,2] fp32

    int n = in_sizes[0] / 2;  // 16384 points
    int threads = 128;
    int blocks = (n + threads - 1) / threads;   // 128 blocks
    VectorP1FunctionSpace_5342939316636_kernel<<<blocks, threads>>>(
        x, wx, wy, out, n);
}